// round 1
// baseline (speedup 1.0000x reference)
#include <cuda_runtime.h>

#define B 8
#define T 2048
#define D 1024
#define HS 64

// ---- device scratch (no cudaMalloc allowed) ----
__device__ float g_q[B * T * HS];            // 4 MB
__device__ float g_k[B * T * HS];            // 4 MB
__device__ float g_v[B * T * HS];            // 4 MB
__device__ float g_s[(size_t)B * T * T];     // 128 MB scores

// =====================================================================
// K1: projections  q = x@Wq^T + bq, k, v.  Rows = B*T = 16384, K = 1024.
// BM=64, BK=16, 256 threads (16x16), each thread 4 rows x 4 cols x 3 mats.
// =====================================================================
__global__ __launch_bounds__(256) void proj_kernel(
    const float* __restrict__ x,
    const float* __restrict__ Wk, const float* __restrict__ bk,
    const float* __restrict__ Wq, const float* __restrict__ bq,
    const float* __restrict__ Wv, const float* __restrict__ bv)
{
    __shared__ float Xs[16][68];
    __shared__ float Ws[3][16][68];

    const int m0  = blockIdx.x * 64;
    const int tid = threadIdx.x;
    const int tm  = tid >> 4;   // 0..15
    const int tn  = tid & 15;   // 0..15

    const float* W[3] = {Wk, Wq, Wv};

    float acc[3][4][4];
#pragma unroll
    for (int m = 0; m < 3; m++)
#pragma unroll
        for (int i = 0; i < 4; i++)
#pragma unroll
            for (int j = 0; j < 4; j++) acc[m][i][j] = 0.f;

    const int lr = tid >> 2;          // 0..63
    const int lc = (tid & 3) << 2;    // 0,4,8,12

    for (int k0 = 0; k0 < D; k0 += 16) {
        float4 xv = *(const float4*)(x + (size_t)(m0 + lr) * D + k0 + lc);
        Xs[lc + 0][lr] = xv.x; Xs[lc + 1][lr] = xv.y;
        Xs[lc + 2][lr] = xv.z; Xs[lc + 3][lr] = xv.w;
#pragma unroll
        for (int m = 0; m < 3; m++) {
            float4 wv = *(const float4*)(W[m] + (size_t)lr * D + k0 + lc);
            Ws[m][lc + 0][lr] = wv.x; Ws[m][lc + 1][lr] = wv.y;
            Ws[m][lc + 2][lr] = wv.z; Ws[m][lc + 3][lr] = wv.w;
        }
        __syncthreads();
#pragma unroll
        for (int kk = 0; kk < 16; kk++) {
            float4 a  = *(const float4*)&Xs[kk][tm << 2];
            float4 b0 = *(const float4*)&Ws[0][kk][tn << 2];
            float4 b1 = *(const float4*)&Ws[1][kk][tn << 2];
            float4 b2 = *(const float4*)&Ws[2][kk][tn << 2];
            float av[4]  = {a.x,  a.y,  a.z,  a.w};
            float bv0[4] = {b0.x, b0.y, b0.z, b0.w};
            float bv1[4] = {b1.x, b1.y, b1.z, b1.w};
            float bv2[4] = {b2.x, b2.y, b2.z, b2.w};
#pragma unroll
            for (int i = 0; i < 4; i++)
#pragma unroll
                for (int j = 0; j < 4; j++) {
                    acc[0][i][j] = fmaf(av[i], bv0[j], acc[0][i][j]);
                    acc[1][i][j] = fmaf(av[i], bv1[j], acc[1][i][j]);
                    acc[2][i][j] = fmaf(av[i], bv2[j], acc[2][i][j]);
                }
        }
        __syncthreads();
    }

    float* outp[3] = {g_k, g_q, g_v};
    const float* bias[3] = {bk, bq, bv};
#pragma unroll
    for (int m = 0; m < 3; m++)
#pragma unroll
        for (int i = 0; i < 4; i++) {
            int row = m0 + (tm << 2) + i;
#pragma unroll
            for (int j = 0; j < 4; j++) {
                int h = (tn << 2) + j;
                outp[m][(size_t)row * HS + h] = acc[m][i][j] + bias[m][h];
            }
        }
}

// =====================================================================
// K2a: S[b,t,v] = 8 * sum_c q[b,t,c] * k[b,v,c]
// BM=BN=64, K=64 (full). grid (T/64, T/64, B). 256 threads, 4x4 microtile.
// =====================================================================
__global__ __launch_bounds__(256) void qk_kernel()
{
    __shared__ float Qs[64][68];
    __shared__ float Ks[64][68];

    const int v0  = blockIdx.x * 64;
    const int t0  = blockIdx.y * 64;
    const int b   = blockIdx.z;
    const int tid = threadIdx.x;
    const int tm  = tid >> 4;
    const int tn  = tid & 15;

    const float* qbase = g_q + (size_t)(b * T + t0) * HS;
    const float* kbase = g_k + (size_t)(b * T + v0) * HS;

#pragma unroll
    for (int it = 0; it < 4; it++) {
        int idx = tid + it * 256;      // 0..1023
        int r   = idx >> 4;            // 0..63
        int c4  = (idx & 15) << 2;     // 0..60
        float4 qv = *(const float4*)(qbase + (size_t)r * HS + c4);
        Qs[c4 + 0][r] = qv.x; Qs[c4 + 1][r] = qv.y;
        Qs[c4 + 2][r] = qv.z; Qs[c4 + 3][r] = qv.w;
        float4 kv = *(const float4*)(kbase + (size_t)r * HS + c4);
        Ks[c4 + 0][r] = kv.x; Ks[c4 + 1][r] = kv.y;
        Ks[c4 + 2][r] = kv.z; Ks[c4 + 3][r] = kv.w;
    }
    __syncthreads();

    float acc[4][4];
#pragma unroll
    for (int i = 0; i < 4; i++)
#pragma unroll
        for (int j = 0; j < 4; j++) acc[i][j] = 0.f;

#pragma unroll
    for (int kk = 0; kk < 64; kk++) {
        float4 a  = *(const float4*)&Qs[kk][tm << 2];
        float4 bb = *(const float4*)&Ks[kk][tn << 2];
        float av[4] = {a.x,  a.y,  a.z,  a.w};
        float bv[4] = {bb.x, bb.y, bb.z, bb.w};
#pragma unroll
        for (int i = 0; i < 4; i++)
#pragma unroll
            for (int j = 0; j < 4; j++)
                acc[i][j] = fmaf(av[i], bv[j], acc[i][j]);
    }

#pragma unroll
    for (int i = 0; i < 4; i++) {
        int trow = t0 + (tm << 2) + i;
        float4 sv = make_float4(8.f * acc[i][0], 8.f * acc[i][1],
                                8.f * acc[i][2], 8.f * acc[i][3]);
        *(float4*)(g_s + ((size_t)(b * T + trow)) * T + v0 + (tn << 2)) = sv;
    }
}

// =====================================================================
// K2b: S[b,t,v] += sum_c q[b,t,c] * rel[t,v,c]   (rel read exactly once)
// grid t = 0..T-1. 256 threads: thread -> (v = tid&127, b-half = tid>>7).
// rel staged in smem as float4 [128v][16c4] with XOR swizzle.
// =====================================================================
__global__ __launch_bounds__(256) void rel_kernel(const float* __restrict__ rel)
{
    __shared__ float4 Rs[128][16];
    __shared__ float4 Qs4[8][16];

    const int t   = blockIdx.x;
    const int tid = threadIdx.x;

    if (tid < 128) {
        int bb = tid >> 4, c4 = tid & 15;
        Qs4[bb][c4] = *(const float4*)(g_q + (size_t)(bb * T + t) * HS + (c4 << 2));
    }

    const int v  = tid & 127;
    const int bh = tid >> 7;     // 0 or 1 -> b in {4*bh .. 4*bh+3}
    const int sw = v & 7;
    const float4* relt = (const float4*)(rel + (size_t)t * T * HS);

    for (int v0 = 0; v0 < T; v0 += 128) {
        __syncthreads();
#pragma unroll
        for (int it = 0; it < 8; it++) {
            int idx = tid + it * 256;          // 0..2047
            int vv  = idx >> 4;                // 0..127
            int c4  = idx & 15;
            Rs[vv][c4 ^ (vv & 7)] = relt[(size_t)(v0 + vv) * 16 + c4];
        }
        __syncthreads();

        float acc0 = 0.f, acc1 = 0.f, acc2 = 0.f, acc3 = 0.f;
#pragma unroll
        for (int c4 = 0; c4 < 16; c4++) {
            float4 r4 = Rs[v][c4 ^ sw];
            float4 q0 = Qs4[bh * 4 + 0][c4];
            float4 q1 = Qs4[bh * 4 + 1][c4];
            float4 q2 = Qs4[bh * 4 + 2][c4];
            float4 q3 = Qs4[bh * 4 + 3][c4];
            acc0 = fmaf(r4.x, q0.x, fmaf(r4.y, q0.y, fmaf(r4.z, q0.z, fmaf(r4.w, q0.w, acc0))));
            acc1 = fmaf(r4.x, q1.x, fmaf(r4.y, q1.y, fmaf(r4.z, q1.z, fmaf(r4.w, q1.w, acc1))));
            acc2 = fmaf(r4.x, q2.x, fmaf(r4.y, q2.y, fmaf(r4.z, q2.z, fmaf(r4.w, q2.w, acc2))));
            acc3 = fmaf(r4.x, q3.x, fmaf(r4.y, q3.y, fmaf(r4.z, q3.z, fmaf(r4.w, q3.w, acc3))));
        }

        size_t base = ((size_t)((bh * 4) * T + t)) * T + v0 + v;
        const size_t bstride = (size_t)T * T;
        g_s[base] += acc0; base += bstride;
        g_s[base] += acc1; base += bstride;
        g_s[base] += acc2; base += bstride;
        g_s[base] += acc3;
    }
}

// =====================================================================
// K3: softmax over v, then out[b,t,h] = sum_v att * v[b,v,h]
// grid (T/16, B). 256 threads. S rows staged in 128KB dynamic smem.
// =====================================================================
__global__ __launch_bounds__(256) void softmax_pv_kernel(float* __restrict__ out)
{
    extern __shared__ float smem[];
    float* att  = smem;                 // 16 * 2048
    float* invl = smem + 16 * 2048;     // 16

    const int t0   = blockIdx.x * 16;
    const int b    = blockIdx.y;
    const int tid  = threadIdx.x;
    const int warp = tid >> 5;
    const int lane = tid & 31;

#pragma unroll
    for (int rr = 0; rr < 2; rr++) {
        int r = warp * 2 + rr;
        const float* srow = g_s + ((size_t)(b * T + t0 + r)) * T;
        float* arow = att + r * 2048;

        float mx = -3.4e38f;
#pragma unroll 8
        for (int i = 0; i < 64; i++) {
            int vi = i * 32 + lane;
            float s = srow[vi];
            arow[vi] = s;
            mx = fmaxf(mx, s);
        }
#pragma unroll
        for (int o = 16; o > 0; o >>= 1)
            mx = fmaxf(mx, __shfl_xor_sync(0xffffffffu, mx, o));

        float sum = 0.f;
#pragma unroll 8
        for (int i = 0; i < 64; i++) {
            int vi = i * 32 + lane;
            float e = __expf(arow[vi] - mx);
            arow[vi] = e;
            sum += e;
        }
#pragma unroll
        for (int o = 16; o > 0; o >>= 1)
            sum += __shfl_xor_sync(0xffffffffu, sum, o);
        if (lane == 0) invl[r] = 1.f / sum;
    }
    __syncthreads();

    // PV: thread -> h = tid&63, rows rg, rg+4, rg+8, rg+12
    const int h  = tid & 63;
    const int rg = tid >> 6;     // 0..3
    const float* vb = g_v + (size_t)(b * T) * HS + h;
    const float* a0 = att + (rg + 0)  * 2048;
    const float* a1 = att + (rg + 4)  * 2048;
    const float* a2 = att + (rg + 8)  * 2048;
    const float* a3 = att + (rg + 12) * 2048;

    float s0 = 0.f, s1 = 0.f, s2 = 0.f, s3 = 0.f;
    for (int v = 0; v < T; v += 8) {
#pragma unroll
        for (int u = 0; u < 8; u++) {
            float vv = vb[(size_t)(v + u) * HS];
            s0 = fmaf(a0[v + u], vv, s0);
            s1 = fmaf(a1[v + u], vv, s1);
            s2 = fmaf(a2[v + u], vv, s2);
            s3 = fmaf(a3[v + u], vv, s3);
        }
    }

    out[(size_t)(b * T + t0 + rg + 0)  * HS + h] = s0 * invl[rg + 0];
    out[(size_t)(b * T + t0 + rg + 4)  * HS + h] = s1 * invl[rg + 4];
    out[(size_t)(b * T + t0 + rg + 8)  * HS + h] = s2 * invl[rg + 8];
    out[(size_t)(b * T + t0 + rg + 12) * HS + h] = s3 * invl[rg + 12];
}

// =====================================================================
extern "C" void kernel_launch(void* const* d_in, const int* in_sizes, int n_in,
                              void* d_out, int out_size)
{
    (void)in_sizes; (void)n_in; (void)out_size;
    const float* x   = (const float*)d_in[0];
    const float* Wk  = (const float*)d_in[1];
    const float* bk  = (const float*)d_in[2];
    const float* Wq  = (const float*)d_in[3];
    const float* bq  = (const float*)d_in[4];
    const float* Wv  = (const float*)d_in[5];
    const float* bv  = (const float*)d_in[6];
    const float* rel = (const float*)d_in[7];
    float* out = (float*)d_out;

    proj_kernel<<<(B * T) / 64, 256>>>(x, Wk, bk, Wq, bq, Wv, bv);
    qk_kernel<<<dim3(T / 64, T / 64, B), 256>>>();
    rel_kernel<<<T, 256>>>(rel);

    const int k3_smem = (16 * 2048 + 16) * sizeof(float);
    cudaFuncSetAttribute(softmax_pv_kernel,
                         cudaFuncAttributeMaxDynamicSharedMemorySize, k3_smem);
    softmax_pv_kernel<<<dim3(T / 16, B), 256, k3_smem>>>(out);
}

// round 2
// speedup vs baseline: 1.3785x; 1.3785x over previous
#include <cuda_runtime.h>

#define B 8
#define T 2048
#define D 1024
#define HS 64

typedef unsigned long long ull;

// ---- device scratch ----
__device__ float g_qT[B * HS * T];           // [b][c][t]
__device__ float g_kT[B * HS * T];           // [b][c][t]
__device__ float g_v [B * T * HS];           // [b][t][h]
__device__ float g_s [(size_t)B * T * T];    // [b][t][v] scores

// ---- packed f32x2 helpers (sm_103a FFMA2) ----
__device__ __forceinline__ ull splat2(float a) {
    ull r; asm("mov.b64 %0, {%1, %1};" : "=l"(r) : "f"(a)); return r;
}
__device__ __forceinline__ ull pack2(float x, float y) {
    ull r; asm("mov.b64 %0, {%1, %2};" : "=l"(r) : "f"(x), "f"(y)); return r;
}
__device__ __forceinline__ void ffma2(ull& d, ull a, ull b) {
    asm("fma.rn.f32x2 %0, %1, %2, %0;" : "+l"(d) : "l"(a), "l"(b));
}
__device__ __forceinline__ float2 unpack2(ull v) {
    float2 f; asm("mov.b64 {%0, %1}, %2;" : "=f"(f.x), "=f"(f.y) : "l"(v)); return f;
}

// =====================================================================
// K1: projections. BM=128 rows, 256 threads, microtile 8t x 4h, 3 mats.
// Writes kT/qT transposed [b][c][t], v normal [b][t][h].
// =====================================================================
__global__ __launch_bounds__(256) void proj_kernel(
    const float* __restrict__ x,
    const float* __restrict__ Wk, const float* __restrict__ bk,
    const float* __restrict__ Wq, const float* __restrict__ bq,
    const float* __restrict__ Wv, const float* __restrict__ bv)
{
    __shared__ float Xs[16 * 128];       // [c][t]
    __shared__ float Ws[3][16 * 64];     // [m][c][h]

    const int m0  = blockIdx.x * 128;
    const int tid = threadIdx.x;
    const int tg  = tid >> 4;   // 0..15 -> t = tg*8
    const int hg  = tid & 15;   // 0..15 -> h = hg*4

    const float* W[3] = {Wk, Wq, Wv};

    ull acc[3][8][2];
#pragma unroll
    for (int m = 0; m < 3; m++)
#pragma unroll
        for (int i = 0; i < 8; i++) { acc[m][i][0] = 0ull; acc[m][i][1] = 0ull; }

    for (int k0 = 0; k0 < D; k0 += 16) {
        // stage X (coalesced gmem; scattered STS is cheap)
#pragma unroll
        for (int it = 0; it < 2; it++) {
            int idx = tid + it * 256;        // 0..511
            int r   = idx >> 2;              // 0..127
            int c4  = (idx & 3) << 2;
            float4 xv = *(const float4*)(x + (size_t)(m0 + r) * D + k0 + c4);
            Xs[(c4 + 0) * 128 + r] = xv.x; Xs[(c4 + 1) * 128 + r] = xv.y;
            Xs[(c4 + 2) * 128 + r] = xv.z; Xs[(c4 + 3) * 128 + r] = xv.w;
        }
        // stage W: each mat exactly 256 float4
#pragma unroll
        for (int m = 0; m < 3; m++) {
            int r  = tid >> 2;               // 0..63
            int c4 = (tid & 3) << 2;
            float4 wv = *(const float4*)(W[m] + (size_t)r * D + k0 + c4);
            Ws[m][(c4 + 0) * 64 + r] = wv.x; Ws[m][(c4 + 1) * 64 + r] = wv.y;
            Ws[m][(c4 + 2) * 64 + r] = wv.z; Ws[m][(c4 + 3) * 64 + r] = wv.w;
        }
        __syncthreads();

#pragma unroll
        for (int kk = 0; kk < 16; kk++) {
            float4 a0 = *(const float4*)&Xs[kk * 128 + tg * 8];
            float4 a1 = *(const float4*)&Xs[kk * 128 + tg * 8 + 4];
            ull as[8] = {splat2(a0.x), splat2(a0.y), splat2(a0.z), splat2(a0.w),
                         splat2(a1.x), splat2(a1.y), splat2(a1.z), splat2(a1.w)};
#pragma unroll
            for (int m = 0; m < 3; m++) {
                float4 w = *(const float4*)&Ws[m][kk * 64 + hg * 4];
                ull w0 = pack2(w.x, w.y), w1 = pack2(w.z, w.w);
#pragma unroll
                for (int i = 0; i < 8; i++) {
                    ffma2(acc[m][i][0], as[i], w0);
                    ffma2(acc[m][i][1], as[i], w1);
                }
            }
        }
        __syncthreads();
    }

    // epilogue
    const float* bias[3] = {bk, bq, bv};
    const int b = m0 >> 11;  // row / T
#pragma unroll
    for (int m = 0; m < 3; m++) {
        float4 bm = *(const float4*)(bias[m] + hg * 4);
        float bb[4] = {bm.x, bm.y, bm.z, bm.w};
#pragma unroll
        for (int i = 0; i < 8; i++) {
            int row = m0 + tg * 8 + i;
            int t   = row & (T - 1);
            float2 v0 = unpack2(acc[m][i][0]);
            float2 v1 = unpack2(acc[m][i][1]);
            float vals[4] = {v0.x + bb[0], v0.y + bb[1], v1.x + bb[2], v1.y + bb[3]};
            if (m == 0) {       // k -> transposed
#pragma unroll
                for (int j = 0; j < 4; j++)
                    g_kT[(size_t)(b * HS + hg * 4 + j) * T + t] = vals[j];
            } else if (m == 1) { // q -> transposed
#pragma unroll
                for (int j = 0; j < 4; j++)
                    g_qT[(size_t)(b * HS + hg * 4 + j) * T + t] = vals[j];
            } else {             // v -> normal
                *(float4*)(g_v + (size_t)row * HS + hg * 4) =
                    make_float4(vals[0], vals[1], vals[2], vals[3]);
            }
        }
    }
}

// =====================================================================
// K2a: S = 8 * q k^T.  BM=BN=128, 256 threads, microtile 8t x 8v.
// =====================================================================
__global__ __launch_bounds__(256) void qk_kernel()
{
    extern __shared__ float4 sm4[];
    float4* Q4 = sm4;             // [64][32]  (c, t4)
    float4* K4 = sm4 + 64 * 32;   // [64][32]  (c, v4)

    const int v0  = blockIdx.x * 128;
    const int t0  = blockIdx.y * 128;
    const int b   = blockIdx.z;
    const int tid = threadIdx.x;

    const float4* qT4 = (const float4*)g_qT;
    const float4* kT4 = (const float4*)g_kT;

#pragma unroll
    for (int it = 0; it < 8; it++) {
        int idx = tid + it * 256;            // 0..2047 == c*32 + x4
        int c = idx >> 5, x4 = idx & 31;
        Q4[idx] = qT4[(size_t)(b * HS + c) * (T / 4) + (t0 >> 2) + x4];
        K4[idx] = kT4[(size_t)(b * HS + c) * (T / 4) + (v0 >> 2) + x4];
    }
    __syncthreads();

    const int tg = tid >> 4;   // t = tg*8
    const int vg = tid & 15;   // v = vg*8

    ull acc[8][4];
#pragma unroll
    for (int i = 0; i < 8; i++)
#pragma unroll
        for (int p = 0; p < 4; p++) acc[i][p] = 0ull;

#pragma unroll 8
    for (int c = 0; c < 64; c++) {
        float4 a0 = Q4[c * 32 + tg * 2];
        float4 a1 = Q4[c * 32 + tg * 2 + 1];
        float4 k0 = K4[c * 32 + vg * 2];
        float4 k1 = K4[c * 32 + vg * 2 + 1];
        ull kp[4] = {pack2(k0.x, k0.y), pack2(k0.z, k0.w),
                     pack2(k1.x, k1.y), pack2(k1.z, k1.w)};
        ull as[8] = {splat2(a0.x), splat2(a0.y), splat2(a0.z), splat2(a0.w),
                     splat2(a1.x), splat2(a1.y), splat2(a1.z), splat2(a1.w)};
#pragma unroll
        for (int i = 0; i < 8; i++)
#pragma unroll
            for (int p = 0; p < 4; p++) ffma2(acc[i][p], as[i], kp[p]);
    }

#pragma unroll
    for (int i = 0; i < 8; i++) {
        int trow = t0 + tg * 8 + i;
        float* srow = g_s + ((size_t)(b * T + trow)) * T + v0 + vg * 8;
        float2 p0 = unpack2(acc[i][0]), p1 = unpack2(acc[i][1]);
        float2 p2 = unpack2(acc[i][2]), p3 = unpack2(acc[i][3]);
        *(float4*)(srow)     = make_float4(8.f * p0.x, 8.f * p0.y, 8.f * p1.x, 8.f * p1.y);
        *(float4*)(srow + 4) = make_float4(8.f * p2.x, 8.f * p2.y, 8.f * p3.x, 8.f * p3.y);
    }
}

// =====================================================================
// K2b: S += q . rel.  grid t, 256 threads = 128 v x 2 bgroups(4b each).
// q packed in registers (pairs over b); R staged swizzled, read once.
// =====================================================================
__global__ __launch_bounds__(256) void rel_kernel(const float* __restrict__ rel)
{
    __shared__ float4 R4[128][16];
    __shared__ float  qs[8][64];

    const int t   = blockIdx.x;
    const int tid = threadIdx.x;

    // stage q[8][64] for this t (scattered scalar loads, tiny)
    {
        int idx = tid;                  // 2 x 256 = 512
#pragma unroll
        for (int it = 0; it < 2; it++) {
            int bb = idx >> 6, c = idx & 63;
            qs[bb][c] = g_qT[(size_t)(bb * HS + c) * T + t];
            idx += 256;
        }
    }
    __syncthreads();

    const int v  = tid & 127;
    const int bg = tid >> 7;          // 0/1 -> b base 4*bg
    const int sw = v & 15;

    ull qp[2][64];
#pragma unroll
    for (int c = 0; c < 64; c++) {
        qp[0][c] = pack2(qs[bg * 4 + 0][c], qs[bg * 4 + 1][c]);
        qp[1][c] = pack2(qs[bg * 4 + 2][c], qs[bg * 4 + 3][c]);
    }

    const float4* relt = (const float4*)(rel + (size_t)t * T * HS);
    const size_t TT = (size_t)T * T;
    const size_t srow = ((size_t)(bg * 4) * T + t) * T;

    for (int v0 = 0; v0 < T; v0 += 128) {
        __syncthreads();
#pragma unroll
        for (int it = 0; it < 8; it++) {
            int idx = tid + it * 256;     // 0..2047
            int vv  = idx >> 4;
            int c4  = idx & 15;
            R4[vv][c4 ^ (vv & 15)] = relt[(size_t)(v0 + vv) * 16 + c4];
        }
        __syncthreads();

        // prefetch S values for RMW
        size_t si = srow + v0 + v;
        float s0 = g_s[si], s1 = g_s[si + TT], s2 = g_s[si + 2 * TT], s3 = g_s[si + 3 * TT];

        ull a0 = 0ull, a1 = 0ull;
#pragma unroll
        for (int c4 = 0; c4 < 16; c4++) {
            float4 r4 = R4[v][c4 ^ sw];
            ull rp;
            rp = splat2(r4.x); ffma2(a0, qp[0][c4 * 4 + 0], rp); ffma2(a1, qp[1][c4 * 4 + 0], rp);
            rp = splat2(r4.y); ffma2(a0, qp[0][c4 * 4 + 1], rp); ffma2(a1, qp[1][c4 * 4 + 1], rp);
            rp = splat2(r4.z); ffma2(a0, qp[0][c4 * 4 + 2], rp); ffma2(a1, qp[1][c4 * 4 + 2], rp);
            rp = splat2(r4.w); ffma2(a0, qp[0][c4 * 4 + 3], rp); ffma2(a1, qp[1][c4 * 4 + 3], rp);
        }
        float2 f0 = unpack2(a0), f1 = unpack2(a1);
        g_s[si]          = s0 + f0.x;
        g_s[si + TT]     = s1 + f0.y;
        g_s[si + 2 * TT] = s2 + f1.x;
        g_s[si + 3 * TT] = s3 + f1.y;
    }
}

// =====================================================================
// K3: softmax + PV. block = (16 t rows, b). 256 threads.
// att stored transposed in smem (stride 17, conflict-free). PV: warp owns
// a 256-v slice, lane owns 4 h (h-paired FFMA2), partials reduced in smem.
// =====================================================================
__global__ __launch_bounds__(256) void soft_pv_kernel(float* __restrict__ out)
{
    extern __shared__ float sm[];
    float* attT = sm;                       // [2048][17]
    float* pout = sm + 2048 * 17;           // [8][16][64]
    float* invl = pout + 8 * 16 * 64;       // [16]

    const int t0   = blockIdx.x * 16;
    const int b    = blockIdx.y;
    const int tid  = threadIdx.x;
    const int w    = tid >> 5;
    const int lane = tid & 31;

    // pass1: row max (float4 reads)
    float mx[2];
#pragma unroll
    for (int rr = 0; rr < 2; rr++) {
        int r = w * 2 + rr;
        const float4* srow4 = (const float4*)(g_s + ((size_t)(b * T + t0 + r)) * T);
        float m = -3.4e38f;
#pragma unroll
        for (int i = 0; i < 16; i++) {
            float4 sv = srow4[i * 32 + lane];
            m = fmaxf(m, fmaxf(fmaxf(sv.x, sv.y), fmaxf(sv.z, sv.w)));
        }
#pragma unroll
        for (int o = 16; o > 0; o >>= 1)
            m = fmaxf(m, __shfl_xor_sync(0xffffffffu, m, o));
        mx[rr] = m;
    }

    // pass2: exp, store transposed, sum
#pragma unroll
    for (int rr = 0; rr < 2; rr++) {
        int r = w * 2 + rr;
        const float* srow = g_s + ((size_t)(b * T + t0 + r)) * T;
        float sum = 0.f;
#pragma unroll 8
        for (int i = 0; i < 64; i++) {
            int vi = i * 32 + lane;
            float e = __expf(srow[vi] - mx[rr]);
            attT[vi * 17 + r] = e;
            sum += e;
        }
#pragma unroll
        for (int o = 16; o > 0; o >>= 1)
            sum += __shfl_xor_sync(0xffffffffu, sum, o);
        if (lane == 0) invl[r] = 1.f / sum;
    }
    __syncthreads();

    // PV: warp w handles v in [w*256, w*256+256)
    const int th = lane >> 4;    // t-half: rows th*8..th*8+7
    const int hg = lane & 15;    // h = hg*4..hg*4+3
    const float4* vb = (const float4*)(g_v + (size_t)b * T * HS) + hg;

    ull acc[8][2];
#pragma unroll
    for (int j = 0; j < 8; j++) { acc[j][0] = 0ull; acc[j][1] = 0ull; }

    const int vbeg = w * 256;
#pragma unroll 2
    for (int v = vbeg; v < vbeg + 256; v++) {
        float4 vv = vb[(size_t)v * 16];
        ull vp0 = pack2(vv.x, vv.y), vp1 = pack2(vv.z, vv.w);
        const float* arow = attT + v * 17 + th * 8;
#pragma unroll
        for (int j = 0; j < 8; j++) {
            ull a = splat2(arow[j]);
            ffma2(acc[j][0], a, vp0);
            ffma2(acc[j][1], a, vp1);
        }
    }

    // store per-warp partials
    float* pw = pout + w * 1024;
#pragma unroll
    for (int j = 0; j < 8; j++) {
        int tt = th * 8 + j;
        float2 x0 = unpack2(acc[j][0]), x1 = unpack2(acc[j][1]);
        *(float4*)(pw + tt * 64 + hg * 4) = make_float4(x0.x, x0.y, x1.x, x1.y);
    }
    __syncthreads();

    // reduce 8 warps, scale, write out
    {
        int tt = tid >> 4;
        int h4 = (tid & 15) * 4;
        float4 s = make_float4(0.f, 0.f, 0.f, 0.f);
#pragma unroll
        for (int w8 = 0; w8 < 8; w8++) {
            float4 p = *(float4*)(pout + w8 * 1024 + tt * 64 + h4);
            s.x += p.x; s.y += p.y; s.z += p.z; s.w += p.w;
        }
        float sc = invl[tt];
        *(float4*)(out + ((size_t)(b * T + t0 + tt)) * HS + h4) =
            make_float4(s.x * sc, s.y * sc, s.z * sc, s.w * sc);
    }
}

// =====================================================================
extern "C" void kernel_launch(void* const* d_in, const int* in_sizes, int n_in,
                              void* d_out, int out_size)
{
    (void)in_sizes; (void)n_in; (void)out_size;
    const float* x   = (const float*)d_in[0];
    const float* Wk  = (const float*)d_in[1];
    const float* bk  = (const float*)d_in[2];
    const float* Wq  = (const float*)d_in[3];
    const float* bq  = (const float*)d_in[4];
    const float* Wv  = (const float*)d_in[5];
    const float* bv  = (const float*)d_in[6];
    const float* rel = (const float*)d_in[7];
    float* out = (float*)d_out;

    proj_kernel<<<(B * T) / 128, 256>>>(x, Wk, bk, Wq, bq, Wv, bv);

    const int qk_smem = 64 * 32 * 2 * sizeof(float4);   // 64 KB
    cudaFuncSetAttribute(qk_kernel, cudaFuncAttributeMaxDynamicSharedMemorySize, qk_smem);
    qk_kernel<<<dim3(T / 128, T / 128, B), 256, qk_smem>>>();

    rel_kernel<<<T, 256>>>(rel);

    const int k3_smem = (2048 * 17 + 8 * 16 * 64 + 16) * sizeof(float);  // ~172 KB
    cudaFuncSetAttribute(soft_pv_kernel, cudaFuncAttributeMaxDynamicSharedMemorySize, k3_smem);
    soft_pv_kernel<<<dim3(T / 16, B), 256, k3_smem>>>(out);
}